// round 16
// baseline (speedup 1.0000x reference)
#include <cuda_runtime.h>
#include <cuda_bf16.h>
#include <math.h>
#include <stdint.h>

// Problem constants
#define BB 8
#define SS 1536
#define DD 1024
#define S2 3072            // 2*SS
#define NCTMAX 24          // max 128-col tiles
#define NUNITS_MAX (BB * NCTMAX * (NCTMAX + 1) / 2)
// exp(sim/T) = exp2(dot * (1/T)*log2(e)),  T = 0.05
#define KEXP 28.853900817779268f

// ---------------- device scratch ----------------
__device__ __align__(16) __nv_bfloat16 g_fb[(size_t)BB * S2 * DD]; // compact bf16 feats
__device__ float g_posexp[BB * SS];
__device__ int   g_cnt[BB];
__device__ int   g_slot[BB * SS];
__device__ __align__(16) float g_ngt[(size_t)BB * S2 * NCTMAX]; // [token][slot] partials
__device__ double g_loss[BB * 4];
__device__ int   g_mstride;   // 1 = uint8 mask, 4 = int32 mask (LSB byte)
__device__ int   g_work;      // work-stealing counter
__device__ int   g_nunits;    // number of valid units
__device__ uint32_t g_units[NUNITS_MAX]; // packed (b<<10)|(rb<<5)|ct

// ---------------- PTX helpers (base sm_80+ instructions only) ----------------
__device__ __forceinline__ uint32_t smem_u32(const void* p) {
    uint32_t a;
    asm("{ .reg .u64 t; cvta.to.shared.u64 t, %1; cvt.u32.u64 %0, t; }" : "=r"(a) : "l"(p));
    return a;
}
#define SWZ128(o) ((o) ^ (((o) >> 3) & 0x70))

#define CP16(dst, src) \
    asm volatile("cp.async.cg.shared.global [%0], [%1], 16;" :: "r"(dst), "l"(src) : "memory")
#define CP_COMMIT() asm volatile("cp.async.commit_group;" ::: "memory")
#define CP_WAIT1()  asm volatile("cp.async.wait_group 1;" ::: "memory")

#define LDSM_X4(r, addr) \
    asm volatile("ldmatrix.sync.aligned.m8n8.x4.shared.b16 {%0,%1,%2,%3}, [%4];" \
        : "=r"((r)[0]), "=r"((r)[1]), "=r"((r)[2]), "=r"((r)[3]) : "r"(addr))

#define MMA16816(d, a, b0v, b1v) \
    asm volatile("mma.sync.aligned.m16n8k16.row.col.f32.bf16.bf16.f32 " \
        "{%0,%1,%2,%3}, {%4,%5,%6,%7}, {%8,%9}, {%0,%1,%2,%3};" \
        : "+f"((d)[0]), "+f"((d)[1]), "+f"((d)[2]), "+f"((d)[3]) \
        : "r"((a)[0]), "r"((a)[1]), "r"((a)[2]), "r"((a)[3]), "r"(b0v), "r"(b1v))

// ---------------- kernel A: detect mask dtype + prefix scan + pad zeroing ----------------
__global__ void kA_scan(const unsigned char* __restrict__ mask) {
    int b = blockIdx.x;
    int tid = threadIdx.x;               // 256 threads
    const int CH = SS / 256;             // 6
    __shared__ int cnts[256];
    __shared__ int s_total;
    __shared__ int s_stride;

    // --- mask dtype detection (every block redundantly; same result) ---
    {
        int c = 0;
        for (int i = tid; i < BB * SS; i += 256) c += mask[i] ? 1 : 0;
        #pragma unroll
        for (int m = 16; m; m >>= 1) c += __shfl_xor_sync(0xffffffffu, c, m);
        if ((tid & 31) == 0) cnts[tid >> 5] = c;
        __syncthreads();
        if (tid == 0) {
            int t = 0;
            #pragma unroll
            for (int i = 0; i < 8; i++) t += cnts[i];
            int st = (t > (BB * SS * 3) / 10) ? 1 : 4;
            s_stride = st;
            g_mstride = st;
        }
        __syncthreads();
    }
    int stride = s_stride;
    __syncthreads();

    unsigned char mv[CH];
    int cnt = 0;
    int base = tid * CH;
    #pragma unroll
    for (int j = 0; j < CH; j++) {
        mv[j] = mask[((size_t)b * SS + base + j) * stride];
        cnt += mv[j] ? 1 : 0;
    }
    cnts[tid] = cnt;
    __syncthreads();
    for (int off = 1; off < 256; off <<= 1) {
        int v = (tid >= off) ? cnts[tid - off] : 0;
        __syncthreads();
        cnts[tid] += v;
        __syncthreads();
    }
    int run = cnts[tid] - cnt;
    #pragma unroll
    for (int j = 0; j < CH; j++) {
        if (mv[j]) g_slot[b * SS + base + j] = run++;
    }
    if (tid == 255) { g_cnt[b] = cnts[255]; s_total = cnts[255]; }
    __syncthreads();

    // zero bf16 pad rows [2*nb, round128(2*nb))
    int n2 = 2 * s_total;
    int pad_end = ((n2 + 127) / 128) * 128;
    if (pad_end > S2) pad_end = S2;
    int nz = (pad_end - n2) * DD / 2;   // uint32 count
    uint32_t* dst = (uint32_t*)(g_fb + ((size_t)b * S2 + n2) * DD);
    for (int i = tid; i < nz; i += 256) dst[i] = 0u;
}

// ---------------- kernel T: build work-unit table (1 block) ----------------
__global__ void kT_units() {
    int tid = threadIdx.x;    // 32
    if (tid < BB) {
        // exclusive prefix of pair counts over batches
        int offs = 0;
        int myn = 0;
        for (int b = 0; b < BB; b++) {
            int nct = (2 * g_cnt[b] + 127) >> 7;
            int pairs = nct * (nct + 1) / 2;
            if (b < tid) offs += pairs;
            if (b == tid) myn = nct;
        }
        int n = offs;
        for (int rb = 0; rb < myn; rb++)
            for (int ct = rb; ct < myn; ct++)
                g_units[n++] = ((uint32_t)tid << 10) | ((uint32_t)rb << 5) | (uint32_t)ct;
        if (tid == BB - 1) { g_nunits = n; g_work = 0; }
    }
}

// ---------------- kernel B: normalize + compact(bf16) + positive pair(fp32) ----------------
// single fused 3-value block reduction (R13 version — known good)
__global__ void kB_norm(const float* __restrict__ h1, const float* __restrict__ h2,
                        const unsigned char* __restrict__ mask) {
    int g = blockIdx.x;
    int b = g / SS, i = g % SS;
    if (!mask[((size_t)b * SS + i) * g_mstride]) return;
    int tid = threadIdx.x;                     // 256 threads, 4 floats each
    int c  = g_slot[b * SS + i];
    int nb = g_cnt[b];

    const float4* p1 = (const float4*)(h1 + ((size_t)b * SS + i) * DD);
    const float4* p2 = (const float4*)(h2 + ((size_t)b * SS + i) * DD);
    float4 v1 = p1[tid];
    float4 v2 = p2[tid];

    float sa = v1.x * v1.x + v1.y * v1.y + v1.z * v1.z + v1.w * v1.w;
    float sb = v2.x * v2.x + v2.y * v2.y + v2.z * v2.z + v2.w * v2.w;
    float sc = v1.x * v2.x + v1.y * v2.y + v1.z * v2.z + v1.w * v2.w;

    __shared__ float sh[3][8];
    int lane = tid & 31, w = tid >> 5;
    #pragma unroll
    for (int m = 16; m; m >>= 1) {
        sa += __shfl_xor_sync(0xffffffffu, sa, m);
        sb += __shfl_xor_sync(0xffffffffu, sb, m);
        sc += __shfl_xor_sync(0xffffffffu, sc, m);
    }
    if (lane == 0) { sh[0][w] = sa; sh[1][w] = sb; sh[2][w] = sc; }
    __syncthreads();
    if (w == 0) {
        float xa = (lane < 8) ? sh[0][lane] : 0.0f;
        float xb = (lane < 8) ? sh[1][lane] : 0.0f;
        float xc = (lane < 8) ? sh[2][lane] : 0.0f;
        #pragma unroll
        for (int m = 4; m; m >>= 1) {
            xa += __shfl_xor_sync(0xffffffffu, xa, m);
            xb += __shfl_xor_sync(0xffffffffu, xb, m);
            xc += __shfl_xor_sync(0xffffffffu, xc, m);
        }
        if (lane == 0) { sh[0][0] = xa; sh[1][0] = xb; sh[2][0] = xc; }
    }
    __syncthreads();
    float ss1 = sh[0][0], ss2 = sh[1][0], dot = sh[2][0];

    float inv1 = 1.0f / fmaxf(sqrtf(ss1), 1e-12f);
    float inv2 = 1.0f / fmaxf(sqrtf(ss2), 1e-12f);

    float4 f1 = make_float4(v1.x * inv1, v1.y * inv1, v1.z * inv1, v1.w * inv1);
    float4 f2 = make_float4(v2.x * inv2, v2.y * inv2, v2.z * inv2, v2.w * inv2);

    __nv_bfloat162 a0 = __floats2bfloat162_rn(f1.x, f1.y);
    __nv_bfloat162 a1 = __floats2bfloat162_rn(f1.z, f1.w);
    __nv_bfloat162 b0 = __floats2bfloat162_rn(f2.x, f2.y);
    __nv_bfloat162 b1 = __floats2bfloat162_rn(f2.z, f2.w);
    uint2 pa = make_uint2(*(uint32_t*)&a0, *(uint32_t*)&a1);
    uint2 pb = make_uint2(*(uint32_t*)&b0, *(uint32_t*)&b1);
    ((uint2*)(g_fb + ((size_t)b * S2 + c) * DD))[tid] = pa;
    ((uint2*)(g_fb + ((size_t)b * S2 + nb + c) * DD))[tid] = pb;

    if (tid == 0) g_posexp[b * SS + c] = exp2f(dot * inv1 * inv2 * KEXP);
}

// ---------------- kernel C: persistent symmetric HMMA Gram -------------------
// Units from precomputed table via atomicAdd (order-only nondeterminism; every
// unit writes unique g_ngt slots -> deterministic output).
// 256 threads, CTA tile 128x128, warp tile 32x64, 3-stage cp.async pipeline.
#define STG 32768u
#define SMC_TOTAL (3 * 32768)

__device__ __forceinline__ void load_stage(uint32_t sbase, int st, const __nv_bfloat16* F,
                                           int r0, int c0, int kc, int tid) {
    uint32_t aof = (uint32_t)st * STG;
    uint32_t bof = aof + 16384u;
    #pragma unroll
    for (int i = 0; i < 4; i++) {
        int v = tid + i * 256;
        int r = v >> 3, c = v & 7;
        const char* srcA = (const char*)F + (((size_t)(r0 + r)) * DD + kc * 64 + c * 8) * 2;
        CP16(sbase + aof + SWZ128(r * 128 + c * 16), srcA);
        const char* srcB = (const char*)F + (((size_t)(c0 + r)) * DD + kc * 64 + c * 8) * 2;
        CP16(sbase + bof + SWZ128(r * 128 + c * 16), srcB);
    }
}

__device__ __forceinline__ void ldsm_frag(uint32_t abase, uint32_t bbase, int s,
                                          int l, int wm, int wn,
                                          uint32_t afr[2][4], uint32_t bfr[4][4]) {
    #pragma unroll
    for (int mi = 0; mi < 2; mi++) {
        uint32_t off = SWZ128((uint32_t)((wm * 32 + mi * 16 + (l & 15)) * 128
                                         + s * 32 + (l >> 4) * 16));
        LDSM_X4(afr[mi], abase + off);
    }
    #pragma unroll
    for (int p = 0; p < 4; p++) {
        uint32_t off = SWZ128((uint32_t)((wn * 64 + p * 16 + ((l >> 4) & 1) * 8
                                         + (l & 7)) * 128
                                         + s * 32 + ((l >> 3) & 1) * 16));
        LDSM_X4(bfr[p], bbase + off);
    }
}

__global__ void __launch_bounds__(256, 1) kC_gram() {
    extern __shared__ char smem[];
    __shared__ int s_u;
    uint32_t sbase = smem_u32(smem);
    int tid = threadIdx.x;
    int wid = tid >> 5, l = tid & 31;
    int wm = wid & 3, wn = wid >> 2;
    int g4 = l >> 2, t4 = l & 3;
    int nunits = g_nunits;

    while (true) {
        if (tid == 0) s_u = atomicAdd(&g_work, 1);
        __syncthreads();          // publishes s_u; fences prior-unit smem reads
        int u = s_u;
        if (u >= nunits) break;

        uint32_t e = g_units[u];
        int b  = (int)(e >> 10);
        int rb = (int)((e >> 5) & 31u);
        int ct = (int)(e & 31u);
        int nb = g_cnt[b];
        int n2 = 2 * nb;
        int r0 = rb << 7, c0 = ct << 7;
        bool doCol = (ct > rb);
        const __nv_bfloat16* F = g_fb + (size_t)b * S2 * DD;

        int rmv[4], rrow[4];
        #pragma unroll
        for (int mi = 0; mi < 2; mi++)
            #pragma unroll
            for (int di = 0; di < 2; di++) {
                int row = r0 + wm * 32 + mi * 16 + di * 8 + g4;
                rrow[mi * 2 + di] = row;
                rmv[mi * 2 + di] = (row < nb) ? row : row - nb;
            }
        float rsum[4] = {0.f, 0.f, 0.f, 0.f};
        float csum[8][2];
        #pragma unroll
        for (int ni = 0; ni < 8; ni++) { csum[ni][0] = 0.f; csum[ni][1] = 0.f; }

        float acc[2][8][4];
        #pragma unroll
        for (int mi = 0; mi < 2; mi++)
            #pragma unroll
            for (int ni = 0; ni < 8; ni++)
                #pragma unroll
                for (int j = 0; j < 4; j++) acc[mi][ni][j] = 0.0f;

        load_stage(sbase, 0, F, r0, c0, 0, tid); CP_COMMIT();
        load_stage(sbase, 1, F, r0, c0, 1, tid); CP_COMMIT();

        for (int kc = 0; kc < 16; kc++) {
            int st = kc % 3;
            CP_WAIT1();            // stage kc arrived
            __syncthreads();       // all warps past stage kc-1 reads; kc visible

            if (kc + 2 < 16) load_stage(sbase, (kc + 2) % 3, F, r0, c0, kc + 2, tid);
            CP_COMMIT();           // keep group accounting fixed

            uint32_t abase = sbase + (uint32_t)st * STG;
            uint32_t bbase = abase + 16384u;

            uint32_t afr[2][2][4], bfr[2][4][4];
            ldsm_frag(abase, bbase, 0, l, wm, wn, afr[0], bfr[0]);
            #pragma unroll
            for (int s = 0; s < 4; s++) {
                int cu = s & 1;
                if (s < 3)
                    ldsm_frag(abase, bbase, s + 1, l, wm, wn, afr[cu ^ 1], bfr[cu ^ 1]);
                #pragma unroll
                for (int mi = 0; mi < 2; mi++)
                    #pragma unroll
                    for (int ni = 0; ni < 8; ni++)
                        MMA16816(acc[mi][ni], afr[cu][mi],
                                 bfr[cu][ni >> 1][(ni & 1) * 2],
                                 bfr[cu][ni >> 1][(ni & 1) * 2 + 1]);
            }
        }

        // epilogue: exp + neg-pair mask; row sums and (off-diag) col sums
        #pragma unroll
        for (int mi = 0; mi < 2; mi++)
            #pragma unroll
            for (int ni = 0; ni < 8; ni++)
                #pragma unroll
                for (int j = 0; j < 4; j++) {
                    int col = c0 + wn * 64 + ni * 8 + t4 * 2 + (j & 1);
                    int cm = (col < nb) ? col : col - nb;
                    int ri = mi * 2 + (j >> 1);
                    if (col < n2 && cm != rmv[ri]) {
                        float e2 = exp2f(acc[mi][ni][j] * KEXP);
                        rsum[ri] += e2;
                        if (doCol && rrow[ri] < n2) csum[ni][j & 1] += e2;
                    }
                }

        #pragma unroll
        for (int j = 0; j < 4; j++) {
            rsum[j] += __shfl_xor_sync(0xffffffffu, rsum[j], 1);
            rsum[j] += __shfl_xor_sync(0xffffffffu, rsum[j], 2);
        }
        if (doCol) {
            #pragma unroll
            for (int ni = 0; ni < 8; ni++)
                #pragma unroll
                for (int jc = 0; jc < 2; jc++) {
                    float v = csum[ni][jc];
                    v += __shfl_xor_sync(0xffffffffu, v, 4);
                    v += __shfl_xor_sync(0xffffffffu, v, 8);
                    v += __shfl_xor_sync(0xffffffffu, v, 16);
                    csum[ni][jc] = v;
                }
        }

        float* red  = (float*)smem;          // [128][2] row partials
        float* red2 = (float*)(smem + 1024); // [4][128] col partials
        __syncthreads();   // stage-buffer reads drained before smem reuse
        if (t4 == 0) {
            #pragma unroll
            for (int mi = 0; mi < 2; mi++)
                #pragma unroll
                for (int di = 0; di < 2; di++) {
                    int rl = wm * 32 + mi * 16 + di * 8 + g4;
                    red[rl * 2 + wn] = rsum[mi * 2 + di];
                }
        }
        if (doCol && l < 4) {   // g4==0 lanes hold full sums; t4 = l
            #pragma unroll
            for (int ni = 0; ni < 8; ni++)
                #pragma unroll
                for (int jc = 0; jc < 2; jc++)
                    red2[wm * 128 + wn * 64 + ni * 8 + l * 2 + jc] = csum[ni][jc];
        }
        __syncthreads();
        if (tid < 128) {
            int row = r0 + tid;
            if (row < n2)
                g_ngt[((size_t)b * S2 + row) * NCTMAX + ct] =
                    red[tid * 2 + 0] + red[tid * 2 + 1];
            if (doCol) {
                int col = c0 + tid;
                if (col < n2)
                    g_ngt[((size_t)b * S2 + col) * NCTMAX + rb] =
                        red2[tid] + red2[128 + tid] + red2[256 + tid] + red2[384 + tid];
            }
        }
        // loop: next unit (top-of-loop __syncthreads fences these accesses)
    }
}

// ---------------- kernel D: per-batch-quarter loss reduction (grid = BB x 4) ----
__global__ void kD_batch() {
    __shared__ double sh[8];
    int b = blockIdx.x;
    int q = blockIdx.y;
    int tid = threadIdx.x;    // 256
    int lane = tid & 31, w = tid >> 5;
    int nb = g_cnt[b];
    int n2 = 2 * nb;
    double local = 0.0;
    for (int idx = q * 256 + tid; idx < n2; idx += 1024) {
        int c = (idx < nb) ? idx : idx - nb;
        float pos = g_posexp[b * SS + c];
        const float4* pn = (const float4*)(g_ngt + ((size_t)b * S2 + idx) * NCTMAX);
        float Ng = 0.0f;
        #pragma unroll
        for (int s = 0; s < NCTMAX / 4; s++) {   // unwritten slots stay 0
            float4 wv = pn[s];
            Ng += wv.x + wv.y + wv.z + wv.w;
        }
        local += (double)log1pf(Ng / pos);
    }
    #pragma unroll
    for (int m = 16; m; m >>= 1) local += __shfl_xor_sync(0xffffffffu, local, m);
    if (lane == 0) sh[w] = local;
    __syncthreads();
    if (w == 0) {
        double x = (lane < 8) ? sh[lane] : 0.0;
        #pragma unroll
        for (int m = 4; m; m >>= 1) x += __shfl_xor_sync(0xffffffffu, x, m);
        if (lane == 0) g_loss[b * 4 + q] = (n2 > 0) ? x / (double)n2 : 0.0;
    }
}

// ---------------- kernel E: combine 32 partials ----------------
__global__ void kE_combine(float* __restrict__ out) {
    if (threadIdx.x == 0) {
        double t = 0.0;
        #pragma unroll
        for (int i = 0; i < BB * 4; i++) t += g_loss[i];
        out[0] = (float)(t / (double)BB);
    }
}

// ---------------- launch ----------------
extern "C" void kernel_launch(void* const* d_in, const int* in_sizes, int n_in,
                              void* d_out, int out_size) {
    const float* h1 = (const float*)d_in[0];
    const float* h2 = (const float*)d_in[1];
    const unsigned char* mask = (const unsigned char*)d_in[2];
    float* out = (float*)d_out;

    static int s_nsm = 0;
    if (!s_nsm) {
        cudaFuncSetAttribute(kC_gram, cudaFuncAttributeMaxDynamicSharedMemorySize, SMC_TOTAL);
        cudaDeviceGetAttribute(&s_nsm, cudaDevAttrMultiProcessorCount, 0);
        if (s_nsm <= 0) s_nsm = 148;
    }

    kA_scan<<<BB, 256>>>(mask);
    kT_units<<<1, 32>>>();
    kB_norm<<<BB * SS, 256>>>(h1, h2, mask);
    kC_gram<<<s_nsm, 256, SMC_TOTAL>>>();
    dim3 gd(BB, 4);
    kD_batch<<<gd, 256>>>();
    kE_combine<<<1, 32>>>(out);
}

// round 17
// speedup vs baseline: 1.3167x; 1.3167x over previous
#include <cuda_runtime.h>
#include <cuda_bf16.h>
#include <math.h>
#include <stdint.h>

// Problem constants
#define BB 8
#define SS 1536
#define DD 1024
#define S2 3072            // 2*SS
#define NCTMAX 24          // max 128-col tiles
#define NPAIRS 300         // NCTMAX*(NCTMAX+1)/2
// exp(sim/T) = exp2(dot * (1/T)*log2(e)),  T = 0.05
#define KEXP 28.853900817779268f

// ---------------- device scratch ----------------
__device__ __align__(16) __nv_bfloat16 g_fb[(size_t)BB * S2 * DD]; // compact bf16 feats
__device__ float g_posexp[BB * SS];
__device__ int   g_cnt[BB];
__device__ int   g_slot[BB * SS];
__device__ __align__(16) float g_ngt[(size_t)BB * S2 * NCTMAX]; // [token][slot] partials
__device__ double g_loss[BB * 4];
__device__ int   g_mstride;   // 1 = uint8 mask, 4 = int32 mask (LSB byte)

// ---------------- PTX helpers (base sm_80+ instructions only) ----------------
__device__ __forceinline__ uint32_t smem_u32(const void* p) {
    uint32_t a;
    asm("{ .reg .u64 t; cvta.to.shared.u64 t, %1; cvt.u32.u64 %0, t; }" : "=r"(a) : "l"(p));
    return a;
}
#define SWZ128(o) ((o) ^ (((o) >> 3) & 0x70))

#define CP16(dst, src) \
    asm volatile("cp.async.cg.shared.global [%0], [%1], 16;" :: "r"(dst), "l"(src) : "memory")
#define CP_COMMIT() asm volatile("cp.async.commit_group;" ::: "memory")
#define CP_WAIT1()  asm volatile("cp.async.wait_group 1;" ::: "memory")

#define LDSM_X4(r, addr) \
    asm volatile("ldmatrix.sync.aligned.m8n8.x4.shared.b16 {%0,%1,%2,%3}, [%4];" \
        : "=r"((r)[0]), "=r"((r)[1]), "=r"((r)[2]), "=r"((r)[3]) : "r"(addr))

#define MMA16816(d, a, b0v, b1v) \
    asm volatile("mma.sync.aligned.m16n8k16.row.col.f32.bf16.bf16.f32 " \
        "{%0,%1,%2,%3}, {%4,%5,%6,%7}, {%8,%9}, {%0,%1,%2,%3};" \
        : "+f"((d)[0]), "+f"((d)[1]), "+f"((d)[2]), "+f"((d)[3]) \
        : "r"((a)[0]), "r"((a)[1]), "r"((a)[2]), "r"((a)[3]), "r"(b0v), "r"(b1v))

// ---------------- kernel A: detect mask dtype + prefix scan + pad zeroing ----------------
__global__ void kA_scan(const unsigned char* __restrict__ mask) {
    int b = blockIdx.x;
    int tid = threadIdx.x;               // 256 threads
    const int CH = SS / 256;             // 6
    __shared__ int cnts[256];
    __shared__ int s_total;
    __shared__ int s_stride;

    // --- mask dtype detection (every block redundantly; same result) ---
    {
        int c = 0;
        for (int i = tid; i < BB * SS; i += 256) c += mask[i] ? 1 : 0;
        #pragma unroll
        for (int m = 16; m; m >>= 1) c += __shfl_xor_sync(0xffffffffu, c, m);
        if ((tid & 31) == 0) cnts[tid >> 5] = c;
        __syncthreads();
        if (tid == 0) {
            int t = 0;
            #pragma unroll
            for (int i = 0; i < 8; i++) t += cnts[i];
            int st = (t > (BB * SS * 3) / 10) ? 1 : 4;
            s_stride = st;
            g_mstride = st;
        }
        __syncthreads();
    }
    int stride = s_stride;
    __syncthreads();

    unsigned char mv[CH];
    int cnt = 0;
    int base = tid * CH;
    #pragma unroll
    for (int j = 0; j < CH; j++) {
        mv[j] = mask[((size_t)b * SS + base + j) * stride];
        cnt += mv[j] ? 1 : 0;
    }
    cnts[tid] = cnt;
    __syncthreads();
    for (int off = 1; off < 256; off <<= 1) {
        int v = (tid >= off) ? cnts[tid - off] : 0;
        __syncthreads();
        cnts[tid] += v;
        __syncthreads();
    }
    int run = cnts[tid] - cnt;
    #pragma unroll
    for (int j = 0; j < CH; j++) {
        if (mv[j]) g_slot[b * SS + base + j] = run++;
    }
    if (tid == 255) { g_cnt[b] = cnts[255]; s_total = cnts[255]; }
    __syncthreads();

    // zero bf16 pad rows [2*nb, round128(2*nb))
    int n2 = 2 * s_total;
    int pad_end = ((n2 + 127) / 128) * 128;
    if (pad_end > S2) pad_end = S2;
    int nz = (pad_end - n2) * DD / 2;   // uint32 count
    uint32_t* dst = (uint32_t*)(g_fb + ((size_t)b * S2 + n2) * DD);
    for (int i = tid; i < nz; i += 256) dst[i] = 0u;
}

// ---------------- kernel B: normalize + compact(bf16) + positive pair(fp32) ----------------
// single fused 3-value block reduction (known good)
__global__ void kB_norm(const float* __restrict__ h1, const float* __restrict__ h2,
                        const unsigned char* __restrict__ mask) {
    int g = blockIdx.x;
    int b = g / SS, i = g % SS;
    if (!mask[((size_t)b * SS + i) * g_mstride]) return;
    int tid = threadIdx.x;                     // 256 threads, 4 floats each
    int c  = g_slot[b * SS + i];
    int nb = g_cnt[b];

    const float4* p1 = (const float4*)(h1 + ((size_t)b * SS + i) * DD);
    const float4* p2 = (const float4*)(h2 + ((size_t)b * SS + i) * DD);
    float4 v1 = p1[tid];
    float4 v2 = p2[tid];

    float sa = v1.x * v1.x + v1.y * v1.y + v1.z * v1.z + v1.w * v1.w;
    float sb = v2.x * v2.x + v2.y * v2.y + v2.z * v2.z + v2.w * v2.w;
    float sc = v1.x * v2.x + v1.y * v2.y + v1.z * v2.z + v1.w * v2.w;

    __shared__ float sh[3][8];
    int lane = tid & 31, w = tid >> 5;
    #pragma unroll
    for (int m = 16; m; m >>= 1) {
        sa += __shfl_xor_sync(0xffffffffu, sa, m);
        sb += __shfl_xor_sync(0xffffffffu, sb, m);
        sc += __shfl_xor_sync(0xffffffffu, sc, m);
    }
    if (lane == 0) { sh[0][w] = sa; sh[1][w] = sb; sh[2][w] = sc; }
    __syncthreads();
    if (w == 0) {
        float xa = (lane < 8) ? sh[0][lane] : 0.0f;
        float xb = (lane < 8) ? sh[1][lane] : 0.0f;
        float xc = (lane < 8) ? sh[2][lane] : 0.0f;
        #pragma unroll
        for (int m = 4; m; m >>= 1) {
            xa += __shfl_xor_sync(0xffffffffu, xa, m);
            xb += __shfl_xor_sync(0xffffffffu, xb, m);
            xc += __shfl_xor_sync(0xffffffffu, xc, m);
        }
        if (lane == 0) { sh[0][0] = xa; sh[1][0] = xb; sh[2][0] = xc; }
    }
    __syncthreads();
    float ss1 = sh[0][0], ss2 = sh[1][0], dot = sh[2][0];

    float inv1 = 1.0f / fmaxf(sqrtf(ss1), 1e-12f);
    float inv2 = 1.0f / fmaxf(sqrtf(ss2), 1e-12f);

    float4 f1 = make_float4(v1.x * inv1, v1.y * inv1, v1.z * inv1, v1.w * inv1);
    float4 f2 = make_float4(v2.x * inv2, v2.y * inv2, v2.z * inv2, v2.w * inv2);

    __nv_bfloat162 a0 = __floats2bfloat162_rn(f1.x, f1.y);
    __nv_bfloat162 a1 = __floats2bfloat162_rn(f1.z, f1.w);
    __nv_bfloat162 b0 = __floats2bfloat162_rn(f2.x, f2.y);
    __nv_bfloat162 b1 = __floats2bfloat162_rn(f2.z, f2.w);
    uint2 pa = make_uint2(*(uint32_t*)&a0, *(uint32_t*)&a1);
    uint2 pb = make_uint2(*(uint32_t*)&b0, *(uint32_t*)&b1);
    ((uint2*)(g_fb + ((size_t)b * S2 + c) * DD))[tid] = pa;
    ((uint2*)(g_fb + ((size_t)b * S2 + nb + c) * DD))[tid] = pb;

    if (tid == 0) g_posexp[b * SS + c] = exp2f(dot * inv1 * inv2 * KEXP);
}

// ---------------- kernel C: symmetric HMMA Gram + fused exp/mask/row+col sums ----
// Grid-based (kept). 512 threads (16 warps), CTA tile 128x128, warp tile 32x32,
// 3-stage cp.async pipeline (K-chunk 64). Off-diagonal tiles scatter row-sums
// (slot ct) AND col-sums (slot rb). Deterministic, no atomics.
#define STG 32768u
#define SMC_TOTAL (3 * 32768)
#define NTHR 512

__device__ __forceinline__ void load_stage(uint32_t sbase, int st, const __nv_bfloat16* F,
                                           int r0, int c0, int kc, int tid) {
    uint32_t aof = (uint32_t)st * STG;
    uint32_t bof = aof + 16384u;
    #pragma unroll
    for (int i = 0; i < 2; i++) {
        int v = tid + i * NTHR;
        int r = v >> 3, c = v & 7;
        const char* srcA = (const char*)F + (((size_t)(r0 + r)) * DD + kc * 64 + c * 8) * 2;
        CP16(sbase + aof + SWZ128(r * 128 + c * 16), srcA);
        const char* srcB = (const char*)F + (((size_t)(c0 + r)) * DD + kc * 64 + c * 8) * 2;
        CP16(sbase + bof + SWZ128(r * 128 + c * 16), srcB);
    }
}

__device__ __forceinline__ void ldsm_frag(uint32_t abase, uint32_t bbase, int s,
                                          int l, int wm, int wn,
                                          uint32_t afr[2][4], uint32_t bfr[2][4]) {
    #pragma unroll
    for (int mi = 0; mi < 2; mi++) {
        uint32_t off = SWZ128((uint32_t)((wm * 32 + mi * 16 + (l & 15)) * 128
                                         + s * 32 + (l >> 4) * 16));
        LDSM_X4(afr[mi], abase + off);
    }
    #pragma unroll
    for (int p = 0; p < 2; p++) {
        uint32_t off = SWZ128((uint32_t)((wn * 32 + p * 16 + ((l >> 4) & 1) * 8
                                         + (l & 7)) * 128
                                         + s * 32 + ((l >> 3) & 1) * 16));
        LDSM_X4(bfr[p], bbase + off);
    }
}

__global__ void __launch_bounds__(NTHR, 1) kC_gram() {
    extern __shared__ char smem[];
    int b = blockIdx.y;
    int nb = g_cnt[b];
    int n2 = 2 * nb;

    // decode pair index -> (rb, ct), 0 <= rb <= ct < NCTMAX
    int p = blockIdx.x;
    int rb = 0;
    while (p >= NCTMAX - rb) { p -= NCTMAX - rb; rb++; }
    int ct = rb + p;

    int r0 = rb << 7, c0 = ct << 7;
    if (c0 >= n2) return;          // ct >= rb, so this covers r0 too
    bool doCol = (ct > rb);

    uint32_t sbase = smem_u32(smem);
    const __nv_bfloat16* F = g_fb + (size_t)b * S2 * DD;
    int tid = threadIdx.x;
    int wid = tid >> 5, l = tid & 31;
    int wm = wid & 3, wn = wid >> 2;     // wm: 4 row groups, wn: 4 col groups
    int g4 = l >> 2, t4 = l & 3;

    // per-thread output rows (mi, di) and validity
    int rmv[4], rrow[4];
    #pragma unroll
    for (int mi = 0; mi < 2; mi++)
        #pragma unroll
        for (int di = 0; di < 2; di++) {
            int row = r0 + wm * 32 + mi * 16 + di * 8 + g4;
            rrow[mi * 2 + di] = row;
            rmv[mi * 2 + di] = (row < nb) ? row : row - nb;
        }
    float rsum[4] = {0.f, 0.f, 0.f, 0.f};
    float csum[4][2];
    #pragma unroll
    for (int ni = 0; ni < 4; ni++) { csum[ni][0] = 0.f; csum[ni][1] = 0.f; }

    float acc[2][4][4];
    #pragma unroll
    for (int mi = 0; mi < 2; mi++)
        #pragma unroll
        for (int ni = 0; ni < 4; ni++)
            #pragma unroll
            for (int j = 0; j < 4; j++) acc[mi][ni][j] = 0.0f;

    load_stage(sbase, 0, F, r0, c0, 0, tid); CP_COMMIT();
    load_stage(sbase, 1, F, r0, c0, 1, tid); CP_COMMIT();

    for (int kc = 0; kc < 16; kc++) {
        int st = kc % 3;
        CP_WAIT1();            // stage kc arrived
        __syncthreads();       // all warps past stage kc-1 reads; kc visible

        if (kc + 2 < 16) load_stage(sbase, (kc + 2) % 3, F, r0, c0, kc + 2, tid);
        CP_COMMIT();           // keep group accounting fixed

        uint32_t abase = sbase + (uint32_t)st * STG;
        uint32_t bbase = abase + 16384u;

        uint32_t afr[2][2][4], bfr[2][2][4];
        ldsm_frag(abase, bbase, 0, l, wm, wn, afr[0], bfr[0]);
        #pragma unroll
        for (int s = 0; s < 4; s++) {
            int cu = s & 1;
            if (s < 3)
                ldsm_frag(abase, bbase, s + 1, l, wm, wn, afr[cu ^ 1], bfr[cu ^ 1]);
            #pragma unroll
            for (int mi = 0; mi < 2; mi++)
                #pragma unroll
                for (int ni = 0; ni < 4; ni++)
                    MMA16816(acc[mi][ni], afr[cu][mi],
                             bfr[cu][ni >> 1][(ni & 1) * 2],
                             bfr[cu][ni >> 1][(ni & 1) * 2 + 1]);
        }
    }

    // epilogue: exp + neg-pair mask; accumulate row sums and (off-diag) col sums
    #pragma unroll
    for (int mi = 0; mi < 2; mi++)
        #pragma unroll
        for (int ni = 0; ni < 4; ni++)
            #pragma unroll
            for (int j = 0; j < 4; j++) {
                int col = c0 + wn * 32 + ni * 8 + t4 * 2 + (j & 1);
                int cm = (col < nb) ? col : col - nb;
                int ri = mi * 2 + (j >> 1);
                if (col < n2 && cm != rmv[ri]) {
                    float e = exp2f(acc[mi][ni][j] * KEXP);
                    rsum[ri] += e;
                    if (doCol && rrow[ri] < n2) csum[ni][j & 1] += e;
                }
            }

    // row sums: reduce over t4 lanes (cols within warp)
    #pragma unroll
    for (int j = 0; j < 4; j++) {
        rsum[j] += __shfl_xor_sync(0xffffffffu, rsum[j], 1);
        rsum[j] += __shfl_xor_sync(0xffffffffu, rsum[j], 2);
    }
    // col sums: reduce over g4 lanes (rows within warp; stride 4, 8, 16)
    if (doCol) {
        #pragma unroll
        for (int ni = 0; ni < 4; ni++)
            #pragma unroll
            for (int jc = 0; jc < 2; jc++) {
                float v = csum[ni][jc];
                v += __shfl_xor_sync(0xffffffffu, v, 4);
                v += __shfl_xor_sync(0xffffffffu, v, 8);
                v += __shfl_xor_sync(0xffffffffu, v, 16);
                csum[ni][jc] = v;
            }
    }

    float* red  = (float*)smem;          // [128][4] row partials (2 KB)
    float* red2 = (float*)(smem + 2048); // [4][128] col partials (2 KB)
    __syncthreads();   // stage-buffer reads fully drained before reuse
    if (t4 == 0) {
        #pragma unroll
        for (int mi = 0; mi < 2; mi++)
            #pragma unroll
            for (int di = 0; di < 2; di++) {
                int rl = wm * 32 + mi * 16 + di * 8 + g4;
                red[rl * 4 + wn] = rsum[mi * 2 + di];
            }
    }
    if (doCol && l < 4) {   // g4 == 0 lanes hold full g4-sums; t4 = l
        #pragma unroll
        for (int ni = 0; ni < 4; ni++)
            #pragma unroll
            for (int jc = 0; jc < 2; jc++)
                red2[wm * 128 + wn * 32 + ni * 8 + l * 2 + jc] = csum[ni][jc];
    }
    __syncthreads();
    if (tid < 128) {
        int row = r0 + tid;
        if (row < n2)
            g_ngt[((size_t)b * S2 + row) * NCTMAX + ct] =
                red[tid * 4 + 0] + red[tid * 4 + 1] + red[tid * 4 + 2] + red[tid * 4 + 3];
        if (doCol) {
            int col = c0 + tid;
            if (col < n2)
                g_ngt[((size_t)b * S2 + col) * NCTMAX + rb] =
                    red2[tid] + red2[128 + tid] + red2[256 + tid] + red2[384 + tid];
        }
    }
}

// ---------------- kernel D: per-batch-quarter loss reduction (grid = BB x 4) ----
__global__ void kD_batch() {
    __shared__ double sh[8];
    int b = blockIdx.x;
    int q = blockIdx.y;
    int tid = threadIdx.x;    // 256
    int lane = tid & 31, w = tid >> 5;
    int nb = g_cnt[b];
    int n2 = 2 * nb;
    double local = 0.0;
    for (int idx = q * 256 + tid; idx < n2; idx += 1024) {
        int c = (idx < nb) ? idx : idx - nb;
        float pos = g_posexp[b * SS + c];
        const float4* pn = (const float4*)(g_ngt + ((size_t)b * S2 + idx) * NCTMAX);
        float Ng = 0.0f;
        #pragma unroll
        for (int s = 0; s < NCTMAX / 4; s++) {   // unwritten slots stay 0
            float4 wv = pn[s];
            Ng += wv.x + wv.y + wv.z + wv.w;
        }
        local += (double)log1pf(Ng / pos);
    }
    #pragma unroll
    for (int m = 16; m; m >>= 1) local += __shfl_xor_sync(0xffffffffu, local, m);
    if (lane == 0) sh[w] = local;
    __syncthreads();
    if (w == 0) {
        double x = (lane < 8) ? sh[lane] : 0.0;
        #pragma unroll
        for (int m = 4; m; m >>= 1) x += __shfl_xor_sync(0xffffffffu, x, m);
        if (lane == 0) g_loss[b * 4 + q] = (n2 > 0) ? x / (double)n2 : 0.0;
    }
}

// ---------------- kernel E: combine 32 partials ----------------
__global__ void kE_combine(float* __restrict__ out) {
    if (threadIdx.x == 0) {
        double t = 0.0;
        #pragma unroll
        for (int i = 0; i < BB * 4; i++) t += g_loss[i];
        out[0] = (float)(t / (double)BB);
    }
}

// ---------------- launch ----------------
extern "C" void kernel_launch(void* const* d_in, const int* in_sizes, int n_in,
                              void* d_out, int out_size) {
    const float* h1 = (const float*)d_in[0];
    const float* h2 = (const float*)d_in[1];
    const unsigned char* mask = (const unsigned char*)d_in[2];
    float* out = (float*)d_out;

    static int s_attr_done = 0;
    if (!s_attr_done) {
        cudaFuncSetAttribute(kC_gram, cudaFuncAttributeMaxDynamicSharedMemorySize, SMC_TOTAL);
        s_attr_done = 1;
    }

    kA_scan<<<BB, 256>>>(mask);
    kB_norm<<<BB * SS, 256>>>(h1, h2, mask);
    dim3 gc(NPAIRS, BB);
    kC_gram<<<gc, NTHR, SMC_TOTAL>>>();
    dim3 gd(BB, 4);
    kD_batch<<<gd, 256>>>();
    kE_combine<<<1, 32>>>(out);
}